// round 10
// baseline (speedup 1.0000x reference)
#include <cuda_runtime.h>
#include <cuda_fp16.h>
#include <cstdint>

// ---------------- problem constants ----------------
constexpr int Bc = 2;
constexpr int Sc = 2048;
constexpr int Hc = 16;
constexpr int Dc = 64;
constexpr int HID = 1024;
constexpr float CE = 0.03125f * 1.44269504088896340736f;  // (1/sqrt(1024)) * log2(e)

// ---------------- device scratch ----------------
__device__ __half   g_q[Bc * Hc * Sc * Dc];        // [B,H,S,D] fp16 (PRE-SCALED by CE)
__device__ __half   g_k[Bc * Hc * Sc * Dc];        // [B,H,S,D] fp16
__device__ __half   g_v[Bc * Hc * Sc * Dc];        // [B,H,S,D] fp16
__device__ __half   g_att[Bc * Sc * HID];          // [B,S,HID] fp16
__device__ __half   g_wo[HID * HID];               // Wo fp16
__device__ uint32_t g_maskp[Bc * Sc * (Sc / 32)];  // bit-packed mask

// ---------------- helpers ----------------
__device__ __forceinline__ uint32_t smem_u32(const void* p) {
    uint32_t a;
    asm("{ .reg .u64 t; cvta.to.shared.u64 t, %1; cvt.u32.u64 %0, t; }" : "=r"(a) : "l"(p));
    return a;
}
__device__ __forceinline__ uint32_t SW(uint32_t x) { return x ^ ((x >> 3) & 0x70); }

__device__ __forceinline__ void ldsm4(uint32_t* r, uint32_t a) {
    asm volatile("ldmatrix.sync.aligned.m8n8.x4.shared.b16 {%0,%1,%2,%3}, [%4];"
                 : "=r"(r[0]), "=r"(r[1]), "=r"(r[2]), "=r"(r[3]) : "r"(a));
}
__device__ __forceinline__ void ldsm4t(uint32_t* r, uint32_t a) {
    asm volatile("ldmatrix.sync.aligned.m8n8.x4.trans.shared.b16 {%0,%1,%2,%3}, [%4];"
                 : "=r"(r[0]), "=r"(r[1]), "=r"(r[2]), "=r"(r[3]) : "r"(a));
}
__device__ __forceinline__ void mma16816(float* c, const uint32_t* a, const uint32_t* b) {
    asm volatile("mma.sync.aligned.m16n8k16.row.col.f32.f16.f16.f32 "
                 "{%0,%1,%2,%3}, {%4,%5,%6,%7}, {%8,%9}, {%0,%1,%2,%3};"
                 : "+f"(c[0]), "+f"(c[1]), "+f"(c[2]), "+f"(c[3])
                 : "r"(a[0]), "r"(a[1]), "r"(a[2]), "r"(a[3]), "r"(b[0]), "r"(b[1]));
}
// f16-accumulator variant: C/D are 2 regs of packed f16x2
__device__ __forceinline__ void mma16816h(uint32_t* c, const uint32_t* a, const uint32_t* b) {
    asm volatile("mma.sync.aligned.m16n8k16.row.col.f16.f16.f16.f16 "
                 "{%0,%1}, {%2,%3,%4,%5}, {%6,%7}, {%0,%1};"
                 : "+r"(c[0]), "+r"(c[1])
                 : "r"(a[0]), "r"(a[1]), "r"(a[2]), "r"(a[3]), "r"(b[0]), "r"(b[1]));
}
__device__ __forceinline__ void cp16(uint32_t d, const void* s) {
    asm volatile("cp.async.cg.shared.global [%0], [%1], 16;" :: "r"(d), "l"(s) : "memory");
}
__device__ __forceinline__ void cp8(uint32_t d, const void* s) {
    asm volatile("cp.async.ca.shared.global [%0], [%1], 8;" :: "r"(d), "l"(s) : "memory");
}
__device__ __forceinline__ void cp_commit() {
    asm volatile("cp.async.commit_group;" ::: "memory");
}
template <int N> __device__ __forceinline__ void cp_wait() {
    asm volatile("cp.async.wait_group %0;" :: "n"(N) : "memory");
}
__device__ __forceinline__ uint32_t ex2_h2(uint32_t x) {
    uint32_t r;
    asm("ex2.approx.f16x2 %0, %1;" : "=r"(r) : "r"(x));
    return r;
}
__device__ __forceinline__ uint32_t hadd2u(uint32_t a, uint32_t b) {
    uint32_t r;
    asm("add.f16x2 %0, %1, %2;" : "=r"(r) : "r"(a), "r"(b));
    return r;
}

// ---------------------------------------------------------------------------
// Kernel 0a: bit-pack the mask
// ---------------------------------------------------------------------------
__global__ __launch_bounds__(256) void pack_mask_kernel(const int* __restrict__ mask) {
    long i = (long)blockIdx.x * 256 + threadIdx.x;
    int v = mask[i];
    uint32_t bal = __ballot_sync(0xffffffffu, v != 0);
    if ((threadIdx.x & 31) == 0) g_maskp[i >> 5] = bal;
}

// ---------------------------------------------------------------------------
// Kernel 0b: convert Wo to fp16 once
// ---------------------------------------------------------------------------
__global__ __launch_bounds__(256) void convert_wo_kernel(const float* __restrict__ Wo) {
    long i = (long)blockIdx.x * 256 + threadIdx.x;
    float4 f = ((const float4*)Wo)[i];
    ((__half2*)g_wo)[i * 2]     = __floats2half2_rn(f.x, f.y);
    ((__half2*)g_wo)[i * 2 + 1] = __floats2half2_rn(f.z, f.w);
}

// ---------------------------------------------------------------------------
// Kernel 1: fused QKV projection with mma.sync (fp16 in, fp32 accum).
// Q output is PRE-SCALED by CE.
// ---------------------------------------------------------------------------
__global__ __launch_bounds__(256) void proj_kernel(
    const float* __restrict__ xq, const float* __restrict__ xk, const float* __restrict__ xv,
    const float* __restrict__ Wq, const float* __restrict__ bq,
    const float* __restrict__ Wk, const float* __restrict__ bk,
    const float* __restrict__ Wv, const float* __restrict__ bv)
{
    __shared__ __half Xs[128 * 64];
    __shared__ __half Ws[64 * 64];
    __shared__ float  bs[64];

    const int which = blockIdx.y;
    const float* X    = (which == 0) ? xq : (which == 1) ? xk : xv;
    const float* Wt   = (which == 0) ? Wq : (which == 1) ? Wk : Wv;
    const float* bias = (which == 0) ? bq : (which == 1) ? bk : bv;
    __half* outp      = (which == 0) ? g_q : (which == 1) ? g_k : g_v;
    const float oscale = (which == 0) ? CE : 1.0f;

    const int tid = threadIdx.x, lane = tid & 31, w = tid >> 5;
    const long R0 = (long)blockIdx.x * 128;

    const uint32_t xb = smem_u32(Xs), wb = smem_u32(Ws);
    const float4* Xg = (const float4*)(X + R0 * 64);
    for (int i = tid; i < 2048; i += 256) {
        float4 f = Xg[i];
        uint32_t off = SW((uint32_t)i * 8);
        *(__half2*)((char*)Xs + off)     = __floats2half2_rn(f.x, f.y);
        *(__half2*)((char*)Xs + off + 4) = __floats2half2_rn(f.z, f.w);
    }
    const float4* Wg = (const float4*)Wt;
    for (int i = tid; i < 1024; i += 256) {
        float4 f = Wg[i];
        uint32_t off = SW((uint32_t)i * 8);
        *(__half2*)((char*)Ws + off)     = __floats2half2_rn(f.x, f.y);
        *(__half2*)((char*)Ws + off + 4) = __floats2half2_rn(f.z, f.w);
    }
    if (tid < 64) bs[tid] = bias[tid];
    __syncthreads();

    const int lr = lane & 7, g = lane >> 3, tq = lane >> 2, tr = lane & 3;
    const int m0 = w * 16;

    uint32_t qa[16];
    #pragma unroll
    for (int kc = 0; kc < 4; kc++)
        ldsm4(qa + kc * 4, xb + SW((m0 + lr + (g & 1) * 8) * 128 + kc * 32 + (g >> 1) * 16));

    float c[8][4] = {};
    #pragma unroll
    for (int nt = 0; nt < 8; nt++) {
        uint32_t bk[8];
        ldsm4(bk,     wb + SW((nt * 8 + lr) * 128 + g * 16));
        ldsm4(bk + 4, wb + SW((nt * 8 + lr) * 128 + g * 16 + 64));
        #pragma unroll
        for (int kc = 0; kc < 4; kc++) mma16816(c[nt], qa + 4 * kc, bk + 2 * kc);
    }

    const long Rw = R0 + m0;
    const int b = (int)(Rw >> 15);
    const int s = (int)((Rw >> 4) & 2047);
    #pragma unroll
    for (int nt = 0; nt < 8; nt++) {
        const int col = nt * 8 + tr * 2;
        const float b0 = bs[col], b1 = bs[col + 1];
        const int hl = tq, hh = tq + 8;
        __half2* lo = (__half2*)(outp + (((long)(b * Hc + hl) * Sc + s) * Dc) + col);
        __half2* hi = (__half2*)(outp + (((long)(b * Hc + hh) * Sc + s) * Dc) + col);
        *lo = __floats2half2_rn((c[nt][0] + b0) * oscale, (c[nt][1] + b1) * oscale);
        *hi = __floats2half2_rn((c[nt][2] + b0) * oscale, (c[nt][3] + b1) * oscale);
    }
}

// ---------------------------------------------------------------------------
// Kernel 2: flash attention. 128-thr CTAs, M=32 rows/warp. Register diet:
// Q fragments re-loaded from persistent smem each k-tile; QK/PV interleaved
// per 32-key half so P fragments cap at 16 regs. Target 3 CTAs/SM.
// smem: Q 16K | mask ring 4x1K | K 3x8K | V 3x8K = 68 KB.
// ---------------------------------------------------------------------------
constexpr int ATT_SMEM = 69632;
constexpr int ATT_MASK = 16384;
constexpr int ATT_K    = 20480;
constexpr int ATT_V    = 45056;

__global__ __launch_bounds__(128, 3) void attn_kernel()
{
    extern __shared__ char sm[];
    const uint32_t sb = smem_u32(sm);
    const int tid = threadIdx.x, lane = tid & 31, w = tid >> 5;
    const int bh = blockIdx.x >> 4, qt = blockIdx.x & 15;
    const int b = bh >> 4, hd = bh & 15;

    const __half* Qg = g_q + ((long)bh * Sc + qt * 128) * Dc;
    const __half* Kg = g_k + (long)bh * Sc * Dc;
    const __half* Vg = g_v + (long)bh * Sc * Dc;
    const uint32_t* Mp = g_maskp + ((long)b * Sc + qt * 128) * (Sc / 32);

    // Q tile (128 rows x 128B = 16KB) -> [0, 16384), persistent
    for (int i = tid; i < 1024; i += 128)
        cp16(sb + (((uint32_t)i * 16) & ~1023u) + SW(((uint32_t)i * 16) & 1023u),
             (const char*)Qg + (long)i * 16);
    cp_commit();   // group "Q"

    const int lr = lane & 7, g = lane >> 3, tq = lane >> 2, tr = lane & 3;
    const int m0 = w * 32;

    auto prefetch = [&](int kt, int slot) {
        const uint32_t kb = sb + ATT_K + slot * 8192;
        const uint32_t vb = sb + ATT_V + slot * 8192;
        const char* kg = (const char*)(Kg + (long)kt * 64 * 64);
        const char* vg = (const char*)(Vg + (long)kt * 64 * 64);
        for (int i = tid; i < 512; i += 128) {
            uint32_t off = (((uint32_t)i * 16) & ~1023u) + SW(((uint32_t)i * 16) & 1023u);
            cp16(kb + off, kg + (long)i * 16);
            cp16(vb + off, vg + (long)i * 16);
        }
        cp8(sb + ATT_MASK + (kt & 3) * 1024 + tid * 8, (const void*)(Mp + (long)tid * 64 + kt * 2));
    };

    prefetch(0, 0); cp_commit();
    prefetch(1, 1); cp_commit();

    // precomputed Q row byte-offsets (before swizzle)
    const uint32_t qrow0 = (uint32_t)(m0 + lr + (g & 1) * 8) * 128 + (g >> 1) * 16;
    const uint32_t qrow1 = qrow0 + 16 * 128;

    float o[2][8][4] = {};
    float l[2][2] = {};
    int ks = 0, ps = 2;

    for (int kt = 0; kt < 32; kt++) {
        cp_wait<1>();
        __syncthreads();

        if (kt < 30) prefetch(kt + 2, ps);
        cp_commit();

        const uint32_t kb = sb + ATT_K + ks * 8192;
        const uint32_t vb = sb + ATT_V + ks * 8192;
        const uint32_t* mrow = (const uint32_t*)(sm + ATT_MASK + (kt & 3) * 1024);

        // Q fragments for this iteration (transient)
        uint32_t qa[2][16];
        #pragma unroll
        for (int kc = 0; kc < 4; kc++) {
            ldsm4(qa[0] + kc * 4, sb + SW(qrow0 + kc * 32));
            ldsm4(qa[1] + kc * 4, sb + SW(qrow1 + kc * 32));
        }

        uint32_t lacc[2][2] = {{0, 0}, {0, 0}};

        // ---- per 32-key half: QK (f16 accum) + exp + mask, then PV ----
        #pragma unroll
        for (int h = 0; h < 2; h++) {
            uint32_t pa[2][8];
            uint32_t wa_m[2], wb_m[2];
            #pragma unroll
            for (int m2 = 0; m2 < 2; m2++) {
                const int ra = m0 + m2 * 16 + tq;
                wa_m[m2] = mrow[ra * 2 + h]       >> (tr * 2);
                wb_m[m2] = mrow[(ra + 8) * 2 + h] >> (tr * 2);
            }
            #pragma unroll
            for (int j = 0; j < 4; j++) {
                const int nt = h * 4 + j;
                uint32_t bkj[8];
                ldsm4(bkj,     kb + SW((nt * 8 + lr) * 128 + g * 16));
                ldsm4(bkj + 4, kb + SW((nt * 8 + lr) * 128 + g * 16 + 64));
                const int sh = j << 3;
                #pragma unroll
                for (int m2 = 0; m2 < 2; m2++) {
                    uint32_t cd[2] = {0u, 0u};
                    #pragma unroll
                    for (int kc = 0; kc < 4; kc++)
                        mma16816h(cd, qa[m2] + 4 * kc, bkj + 2 * kc);
                    const uint32_t wa = wa_m[m2] >> sh;
                    const uint32_t wbv = wb_m[m2] >> sh;
                    const uint32_t keep01 = ((wa & 1u)  ? 0x0000FFFFu : 0u) |
                                            ((wa & 2u)  ? 0xFFFF0000u : 0u);
                    const uint32_t keep23 = ((wbv & 1u) ? 0x0000FFFFu : 0u) |
                                            ((wbv & 2u) ? 0xFFFF0000u : 0u);
                    uint32_t p01 = ex2_h2(cd[0]) & keep01;
                    uint32_t p23 = ex2_h2(cd[1]) & keep23;
                    pa[m2][j * 2]     = p01;
                    pa[m2][j * 2 + 1] = p23;
                    lacc[m2][0] = hadd2u(lacc[m2][0], p01);
                    lacc[m2][1] = hadd2u(lacc[m2][1], p23);
                }
            }

            // PV for this half: V rows h*32..h*32+31
            #pragma unroll
            for (int nt = 0; nt < 8; nt++) {
                uint32_t bv[4];
                ldsm4t(bv, vb + SW((g * 8 + lr + 32 * h) * 128 + nt * 16));
                #pragma unroll
                for (int m2 = 0; m2 < 2; m2++) {
                    mma16816(o[m2][nt], pa[m2],     bv);
                    mma16816(o[m2][nt], pa[m2] + 4, bv + 2);
                }
            }
        }

        #pragma unroll
        for (int m2 = 0; m2 < 2; m2++) {
            float2 f0 = __half22float2(*reinterpret_cast<__half2*>(&lacc[m2][0]));
            float2 f1 = __half22float2(*reinterpret_cast<__half2*>(&lacc[m2][1]));
            l[m2][0] += f0.x + f0.y;
            l[m2][1] += f1.x + f1.y;
        }

        if (++ks == 3) ks = 0;
        if (++ps == 3) ps = 0;
    }

    #pragma unroll
    for (int m2 = 0; m2 < 2; m2++) {
        #pragma unroll
        for (int i = 0; i < 2; i++) {
            l[m2][i] += __shfl_xor_sync(0xffffffffu, l[m2][i], 1);
            l[m2][i] += __shfl_xor_sync(0xffffffffu, l[m2][i], 2);
        }
        const float inv0 = 1.0f / l[m2][0], inv1 = 1.0f / l[m2][1];
        const int rl = qt * 128 + m0 + m2 * 16 + tq;
        __half* og = g_att + ((long)b * Sc + rl) * HID + hd * 64;
        #pragma unroll
        for (int nt = 0; nt < 8; nt++) {
            const int col = nt * 8 + tr * 2;
            *(__half2*)(og + col)           = __floats2half2_rn(o[m2][nt][0] * inv0, o[m2][nt][1] * inv0);
            *(__half2*)(og + 8 * HID + col) = __floats2half2_rn(o[m2][nt][2] * inv1, o[m2][nt][3] * inv1);
        }
    }
}

// ---------------------------------------------------------------------------
// Kernel 3: out = att @ Wo^T + bo, fp16 GEMM (R8 version: 256 thr, M=16/warp).
// ---------------------------------------------------------------------------
constexpr int OP_SMEM = 65536;

__global__ __launch_bounds__(256, 2) void outproj_kernel(
    const float* __restrict__ bo, float* __restrict__ out)
{
    extern __shared__ char sm[];
    const uint32_t sb = smem_u32(sm);
    const int tid = threadIdx.x, lane = tid & 31, w = tid >> 5;
    const int r0 = blockIdx.x * 128, c0 = blockIdx.y * 128;
    const int lr = lane & 7, g = lane >> 3, tq = lane >> 2, tr = lane & 3;
    const int m0 = w * 16;

    auto prefetch = [&](int kt) {
        const uint32_t base = sb + (kt & 1) * 32768;
        const char* ag = (const char*)(g_att + (long)r0 * HID + kt * 64);
        const char* bg = (const char*)(g_wo  + (long)c0 * HID + kt * 64);
        for (int i = tid; i < 1024; i += 256) {
            const int row = i >> 3, q = i & 7;
            const uint32_t off = SW((uint32_t)(row * 128 + q * 16));
            cp16(base + off,         ag + (long)row * (HID * 2) + q * 16);
            cp16(base + 16384 + off, bg + (long)row * (HID * 2) + q * 16);
        }
    };

    prefetch(0);
    cp_commit();

    float c[16][4] = {};

    for (int kt = 0; kt < 16; kt++) {
        if (kt < 15) { prefetch(kt + 1); cp_commit(); cp_wait<1>(); }
        else         { cp_wait<0>(); }
        __syncthreads();

        const uint32_t ab = sb + (kt & 1) * 32768;
        const uint32_t bb = ab + 16384;

        uint32_t aa[16];
        #pragma unroll
        for (int kc = 0; kc < 4; kc++)
            ldsm4(aa + kc * 4, ab + SW((m0 + lr + (g & 1) * 8) * 128 + kc * 32 + (g >> 1) * 16));

        #pragma unroll
        for (int nt = 0; nt < 16; nt++) {
            uint32_t bbr[8];
            ldsm4(bbr,     bb + SW((nt * 8 + lr) * 128 + g * 16));
            ldsm4(bbr + 4, bb + SW((nt * 8 + lr) * 128 + g * 16 + 64));
            #pragma unroll
            for (int kc = 0; kc < 4; kc++) mma16816(c[nt], aa + 4 * kc, bbr + 2 * kc);
        }
        __syncthreads();
    }

    const int rl = r0 + m0 + tq;
    #pragma unroll
    for (int nt = 0; nt < 16; nt++) {
        const int col = c0 + nt * 8 + tr * 2;
        const float b0 = bo[col], b1 = bo[col + 1];
        *(float2*)(out + (long)rl * HID + col)       = make_float2(c[nt][0] + b0, c[nt][1] + b1);
        *(float2*)(out + (long)(rl + 8) * HID + col) = make_float2(c[nt][2] + b0, c[nt][3] + b1);
    }
}

// ---------------------------------------------------------------------------
extern "C" void kernel_launch(void* const* d_in, const int* in_sizes, int n_in,
                              void* d_out, int out_size)
{
    const float* q    = (const float*)d_in[0];
    const float* k    = (const float*)d_in[1];
    const float* v    = (const float*)d_in[2];
    const int*   mask = (const int*)  d_in[3];
    const float* Wq   = (const float*)d_in[4];
    const float* bq   = (const float*)d_in[5];
    const float* Wk   = (const float*)d_in[6];
    const float* bk   = (const float*)d_in[7];
    const float* Wv   = (const float*)d_in[8];
    const float* bv   = (const float*)d_in[9];
    const float* Wo   = (const float*)d_in[10];
    const float* bo   = (const float*)d_in[11];
    float* out = (float*)d_out;

    cudaFuncSetAttribute(attn_kernel, cudaFuncAttributeMaxDynamicSharedMemorySize, ATT_SMEM);
    cudaFuncSetAttribute(outproj_kernel, cudaFuncAttributeMaxDynamicSharedMemorySize, OP_SMEM);

    pack_mask_kernel<<<Bc * Sc * Sc / 256, 256>>>(mask);
    convert_wo_kernel<<<HID * HID / 4 / 256, 256>>>(Wo);
    proj_kernel<<<dim3(512, 3), 256>>>(q, k, v, Wq, bq, Wk, bk, Wv, bv);
    attn_kernel<<<512, 128, ATT_SMEM>>>();
    outproj_kernel<<<dim3(32, 8), 256, OP_SMEM>>>(bo, out);
}

// round 11
// speedup vs baseline: 1.1396x; 1.1396x over previous
#include <cuda_runtime.h>
#include <cuda_fp16.h>
#include <cstdint>

// ---------------- problem constants ----------------
constexpr int Bc = 2;
constexpr int Sc = 2048;
constexpr int Hc = 16;
constexpr int Dc = 64;
constexpr int HID = 1024;
constexpr float CE = 0.03125f * 1.44269504088896340736f;  // (1/sqrt(1024)) * log2(e)

// ---------------- device scratch ----------------
__device__ __half   g_q[Bc * Hc * Sc * Dc];        // [B,H,S,D] fp16 (PRE-SCALED by CE)
__device__ __half   g_k[Bc * Hc * Sc * Dc];        // [B,H,S,D] fp16
__device__ __half   g_v[Bc * Hc * Sc * Dc];        // [B,H,S,D] fp16
__device__ __half   g_att[Bc * Sc * HID];          // [B,S,HID] fp16
__device__ __half   g_wo[HID * HID];               // Wo fp16
__device__ uint32_t g_maskp[Bc * Sc * (Sc / 32)];  // bit-packed mask

// ---------------- helpers ----------------
__device__ __forceinline__ uint32_t smem_u32(const void* p) {
    uint32_t a;
    asm("{ .reg .u64 t; cvta.to.shared.u64 t, %1; cvt.u32.u64 %0, t; }" : "=r"(a) : "l"(p));
    return a;
}
__device__ __forceinline__ uint32_t SW(uint32_t x) { return x ^ ((x >> 3) & 0x70); }

__device__ __forceinline__ void ldsm4(uint32_t* r, uint32_t a) {
    asm volatile("ldmatrix.sync.aligned.m8n8.x4.shared.b16 {%0,%1,%2,%3}, [%4];"
                 : "=r"(r[0]), "=r"(r[1]), "=r"(r[2]), "=r"(r[3]) : "r"(a));
}
__device__ __forceinline__ void ldsm4t(uint32_t* r, uint32_t a) {
    asm volatile("ldmatrix.sync.aligned.m8n8.x4.trans.shared.b16 {%0,%1,%2,%3}, [%4];"
                 : "=r"(r[0]), "=r"(r[1]), "=r"(r[2]), "=r"(r[3]) : "r"(a));
}
__device__ __forceinline__ void mma16816(float* c, const uint32_t* a, const uint32_t* b) {
    asm volatile("mma.sync.aligned.m16n8k16.row.col.f32.f16.f16.f32 "
                 "{%0,%1,%2,%3}, {%4,%5,%6,%7}, {%8,%9}, {%0,%1,%2,%3};"
                 : "+f"(c[0]), "+f"(c[1]), "+f"(c[2]), "+f"(c[3])
                 : "r"(a[0]), "r"(a[1]), "r"(a[2]), "r"(a[3]), "r"(b[0]), "r"(b[1]));
}
// f16-accumulator variant
__device__ __forceinline__ void mma16816h(uint32_t* c, const uint32_t* a, const uint32_t* b) {
    asm volatile("mma.sync.aligned.m16n8k16.row.col.f16.f16.f16.f16 "
                 "{%0,%1}, {%2,%3,%4,%5}, {%6,%7}, {%0,%1};"
                 : "+r"(c[0]), "+r"(c[1])
                 : "r"(a[0]), "r"(a[1]), "r"(a[2]), "r"(a[3]), "r"(b[0]), "r"(b[1]));
}
__device__ __forceinline__ void cp16(uint32_t d, const void* s) {
    asm volatile("cp.async.cg.shared.global [%0], [%1], 16;" :: "r"(d), "l"(s) : "memory");
}
__device__ __forceinline__ void cp8(uint32_t d, const void* s) {
    asm volatile("cp.async.ca.shared.global [%0], [%1], 8;" :: "r"(d), "l"(s) : "memory");
}
__device__ __forceinline__ void cp_commit() {
    asm volatile("cp.async.commit_group;" ::: "memory");
}
template <int N> __device__ __forceinline__ void cp_wait() {
    asm volatile("cp.async.wait_group %0;" :: "n"(N) : "memory");
}
__device__ __forceinline__ uint32_t ex2_h2(uint32_t x) {
    uint32_t r;
    asm("ex2.approx.f16x2 %0, %1;" : "=r"(r) : "r"(x));
    return r;
}
__device__ __forceinline__ uint32_t hadd2u(uint32_t a, uint32_t b) {
    uint32_t r;
    asm("add.f16x2 %0, %1, %2;" : "=r"(r) : "r"(a), "r"(b));
    return r;
}

// ---------------------------------------------------------------------------
// Fused prologue kernel: blocks [0,1536) QKV projection, [1536,5632) mask
// pack, [5632,6656) Wo convert. One launch; memory-bound parts overlap the
// compute-bound projection.
// ---------------------------------------------------------------------------
constexpr int PRO_PROJ_BLOCKS = 1536;   // 3 x 512
constexpr int PRO_PACK_BLOCKS = 4096;   // 8.4M elems / (256 thr * 8 elems)
constexpr int PRO_CONV_BLOCKS = 1024;   // 1M floats / (256 thr * 4)
constexpr int PRO_GRID = PRO_PROJ_BLOCKS + PRO_PACK_BLOCKS + PRO_CONV_BLOCKS;

__global__ __launch_bounds__(256) void prologue_kernel(
    const float* __restrict__ xq, const float* __restrict__ xk, const float* __restrict__ xv,
    const float* __restrict__ Wq, const float* __restrict__ bq,
    const float* __restrict__ Wk, const float* __restrict__ bk,
    const float* __restrict__ Wv, const float* __restrict__ bv,
    const int* __restrict__ mask, const float* __restrict__ Wo)
{
    const int bid = blockIdx.x;
    const int tid = threadIdx.x;

    if (bid >= PRO_PROJ_BLOCKS + PRO_PACK_BLOCKS) {
        // ---- Wo fp32 -> fp16 ----
        long i = (long)(bid - PRO_PROJ_BLOCKS - PRO_PACK_BLOCKS) * 256 + tid;
        float4 f = ((const float4*)Wo)[i];
        ((__half2*)g_wo)[i * 2]     = __floats2half2_rn(f.x, f.y);
        ((__half2*)g_wo)[i * 2 + 1] = __floats2half2_rn(f.z, f.w);
        return;
    }
    if (bid >= PRO_PROJ_BLOCKS) {
        // ---- mask bit-pack: 8 elems -> 1 byte per thread ----
        long t = (long)(bid - PRO_PROJ_BLOCKS) * 256 + tid;
        const int4* mp = (const int4*)(mask + t * 8);
        int4 a = mp[0], b = mp[1];
        uint32_t byte =
            (uint32_t)(a.x != 0)       | ((uint32_t)(a.y != 0) << 1) |
            ((uint32_t)(a.z != 0) << 2) | ((uint32_t)(a.w != 0) << 3) |
            ((uint32_t)(b.x != 0) << 4) | ((uint32_t)(b.y != 0) << 5) |
            ((uint32_t)(b.z != 0) << 6) | ((uint32_t)(b.w != 0) << 7);
        ((uint8_t*)g_maskp)[t] = (uint8_t)byte;
        return;
    }

    // ---- QKV projection (fp16 mma; Q pre-scaled by CE) ----
    __shared__ __half Xs[128 * 64];
    __shared__ __half Ws[64 * 64];
    __shared__ float  bs[64];

    const int which = bid >> 9;          // 0..2
    const int bx = bid & 511;
    const float* X    = (which == 0) ? xq : (which == 1) ? xk : xv;
    const float* Wt   = (which == 0) ? Wq : (which == 1) ? Wk : Wv;
    const float* bias = (which == 0) ? bq : (which == 1) ? bk : bv;
    __half* outp      = (which == 0) ? g_q : (which == 1) ? g_k : g_v;
    const float oscale = (which == 0) ? CE : 1.0f;

    const int lane = tid & 31, w = tid >> 5;
    const long R0 = (long)bx * 128;

    const uint32_t xb = smem_u32(Xs), wb = smem_u32(Ws);
    const float4* Xg = (const float4*)(X + R0 * 64);
    for (int i = tid; i < 2048; i += 256) {
        float4 f = Xg[i];
        uint32_t off = SW((uint32_t)i * 8);
        *(__half2*)((char*)Xs + off)     = __floats2half2_rn(f.x, f.y);
        *(__half2*)((char*)Xs + off + 4) = __floats2half2_rn(f.z, f.w);
    }
    const float4* Wg = (const float4*)Wt;
    for (int i = tid; i < 1024; i += 256) {
        float4 f = Wg[i];
        uint32_t off = SW((uint32_t)i * 8);
        *(__half2*)((char*)Ws + off)     = __floats2half2_rn(f.x, f.y);
        *(__half2*)((char*)Ws + off + 4) = __floats2half2_rn(f.z, f.w);
    }
    if (tid < 64) bs[tid] = bias[tid];
    __syncthreads();

    const int lr = lane & 7, g = lane >> 3, tq = lane >> 2, tr = lane & 3;
    const int m0 = w * 16;

    uint32_t qa[16];
    #pragma unroll
    for (int kc = 0; kc < 4; kc++)
        ldsm4(qa + kc * 4, xb + SW((m0 + lr + (g & 1) * 8) * 128 + kc * 32 + (g >> 1) * 16));

    float c[8][4] = {};
    #pragma unroll
    for (int nt = 0; nt < 8; nt++) {
        uint32_t bk[8];
        ldsm4(bk,     wb + SW((nt * 8 + lr) * 128 + g * 16));
        ldsm4(bk + 4, wb + SW((nt * 8 + lr) * 128 + g * 16 + 64));
        #pragma unroll
        for (int kc = 0; kc < 4; kc++) mma16816(c[nt], qa + 4 * kc, bk + 2 * kc);
    }

    const long Rw = R0 + m0;
    const int b = (int)(Rw >> 15);
    const int s = (int)((Rw >> 4) & 2047);
    #pragma unroll
    for (int nt = 0; nt < 8; nt++) {
        const int col = nt * 8 + tr * 2;
        const float b0 = bs[col], b1 = bs[col + 1];
        const int hl = tq, hh = tq + 8;
        __half2* lo = (__half2*)(outp + (((long)(b * Hc + hl) * Sc + s) * Dc) + col);
        __half2* hi = (__half2*)(outp + (((long)(b * Hc + hh) * Sc + s) * Dc) + col);
        *lo = __floats2half2_rn((c[nt][0] + b0) * oscale, (c[nt][1] + b1) * oscale);
        *hi = __floats2half2_rn((c[nt][2] + b0) * oscale, (c[nt][3] + b1) * oscale);
    }
}

// ---------------------------------------------------------------------------
// Kernel 2: flash attention (R8 best version). 128-thr CTAs, M=32 rows/warp,
// f16-accum QK MMA, exact mask via AND-zero of p, 3-stage ring.
// smem: Q staging 16K (reused as 4-slot mask ring) | K 3x8K | V 3x8K = 64 KB.
// ---------------------------------------------------------------------------
constexpr int ATT_SMEM = 65536;

__global__ __launch_bounds__(128, 2) void attn_kernel()
{
    extern __shared__ char sm[];
    const uint32_t sb = smem_u32(sm);
    const int tid = threadIdx.x, lane = tid & 31, w = tid >> 5;
    const int bh = blockIdx.x >> 4, qt = blockIdx.x & 15;
    const int b = bh >> 4, hd = bh & 15;

    const __half* Qg = g_q + ((long)bh * Sc + qt * 128) * Dc;
    const __half* Kg = g_k + (long)bh * Sc * Dc;
    const __half* Vg = g_v + (long)bh * Sc * Dc;
    const uint32_t* Mp = g_maskp + ((long)b * Sc + qt * 128) * (Sc / 32);

    // ---- prologue: Q tile (128 rows x 128B = 16KB) into [0, 16384) ----
    for (int i = tid; i < 1024; i += 128)
        cp16(sb + (((uint32_t)i * 16) & ~1023u) + SW(((uint32_t)i * 16) & 1023u),
             (const char*)Qg + (long)i * 16);
    cp_commit();
    cp_wait<0>();
    __syncthreads();

    const int lr = lane & 7, g = lane >> 3, tq = lane >> 2, tr = lane & 3;
    const int m0 = w * 32;

    uint32_t qa[2][16];
    #pragma unroll
    for (int m2 = 0; m2 < 2; m2++)
        #pragma unroll
        for (int kc = 0; kc < 4; kc++)
            ldsm4(qa[m2] + kc * 4,
                  sb + SW((m0 + m2 * 16 + lr + (g & 1) * 8) * 128 + kc * 32 + (g >> 1) * 16));
    __syncthreads();   // Q area dead -> mask ring (4 x 1KB)

    auto prefetch = [&](int kt, int slot) {
        const uint32_t kb = sb + 16384 + slot * 8192;
        const uint32_t vb = sb + 40960 + slot * 8192;
        const char* kg = (const char*)(Kg + (long)kt * 64 * 64);
        const char* vg = (const char*)(Vg + (long)kt * 64 * 64);
        for (int i = tid; i < 512; i += 128) {
            uint32_t off = (((uint32_t)i * 16) & ~1023u) + SW(((uint32_t)i * 16) & 1023u);
            cp16(kb + off, kg + (long)i * 16);
            cp16(vb + off, vg + (long)i * 16);
        }
        cp8(sb + (kt & 3) * 1024 + tid * 8, (const void*)(Mp + (long)tid * 64 + kt * 2));
    };

    prefetch(0, 0); cp_commit();
    prefetch(1, 1); cp_commit();

    float o[2][8][4] = {};
    float l[2][2] = {};
    int ks = 0, ps = 2;

    for (int kt = 0; kt < 32; kt++) {
        cp_wait<1>();
        __syncthreads();

        if (kt < 30) prefetch(kt + 2, ps);
        cp_commit();

        const uint32_t kb = sb + 16384 + ks * 8192;
        const uint32_t vb = sb + 40960 + ks * 8192;
        const uint32_t* mrow = (const uint32_t*)(sm + (kt & 3) * 1024);

        uint32_t pa[2][16];
        uint32_t lacc[2][2] = {{0, 0}, {0, 0}};

        // ---- QK (f16 accum) + exp + mask-zero, two N-halves ----
        #pragma unroll
        for (int h = 0; h < 2; h++) {
            uint32_t wa_m[2], wb_m[2];
            #pragma unroll
            for (int m2 = 0; m2 < 2; m2++) {
                const int ra = m0 + m2 * 16 + tq;
                wa_m[m2] = mrow[ra * 2 + h]       >> (tr * 2);
                wb_m[m2] = mrow[(ra + 8) * 2 + h] >> (tr * 2);
            }
            #pragma unroll
            for (int j = 0; j < 4; j++) {
                const int nt = h * 4 + j;
                uint32_t bkj[8];
                ldsm4(bkj,     kb + SW((nt * 8 + lr) * 128 + g * 16));
                ldsm4(bkj + 4, kb + SW((nt * 8 + lr) * 128 + g * 16 + 64));
                const int sh = j << 3;
                #pragma unroll
                for (int m2 = 0; m2 < 2; m2++) {
                    uint32_t cd[2] = {0u, 0u};
                    #pragma unroll
                    for (int kc = 0; kc < 4; kc++)
                        mma16816h(cd, qa[m2] + 4 * kc, bkj + 2 * kc);
                    const uint32_t wa = wa_m[m2] >> sh;
                    const uint32_t wbv = wb_m[m2] >> sh;
                    const uint32_t keep01 = ((wa & 1u)  ? 0x0000FFFFu : 0u) |
                                            ((wa & 2u)  ? 0xFFFF0000u : 0u);
                    const uint32_t keep23 = ((wbv & 1u) ? 0x0000FFFFu : 0u) |
                                            ((wbv & 2u) ? 0xFFFF0000u : 0u);
                    uint32_t p01 = ex2_h2(cd[0]) & keep01;
                    uint32_t p23 = ex2_h2(cd[1]) & keep23;
                    pa[m2][nt * 2]     = p01;
                    pa[m2][nt * 2 + 1] = p23;
                    lacc[m2][0] = hadd2u(lacc[m2][0], p01);
                    lacc[m2][1] = hadd2u(lacc[m2][1], p23);
                }
            }
        }

        #pragma unroll
        for (int m2 = 0; m2 < 2; m2++) {
            float2 f0 = __half22float2(*reinterpret_cast<__half2*>(&lacc[m2][0]));
            float2 f1 = __half22float2(*reinterpret_cast<__half2*>(&lacc[m2][1]));
            l[m2][0] += f0.x + f0.y;
            l[m2][1] += f1.x + f1.y;
        }

        // ---- O += P @ V (fp32 accum) ----
        #pragma unroll
        for (int nt = 0; nt < 8; nt++) {
            uint32_t bv[8];
            ldsm4t(bv,     vb + SW((g * 8 + lr) * 128 + nt * 16));
            ldsm4t(bv + 4, vb + SW((g * 8 + lr + 32) * 128 + nt * 16));
            #pragma unroll
            for (int m2 = 0; m2 < 2; m2++)
                #pragma unroll
                for (int kc = 0; kc < 4; kc++)
                    mma16816(o[m2][nt], pa[m2] + 4 * kc, bv + 2 * kc);
        }

        if (++ks == 3) ks = 0;
        if (++ps == 3) ps = 0;
    }

    #pragma unroll
    for (int m2 = 0; m2 < 2; m2++) {
        #pragma unroll
        for (int i = 0; i < 2; i++) {
            l[m2][i] += __shfl_xor_sync(0xffffffffu, l[m2][i], 1);
            l[m2][i] += __shfl_xor_sync(0xffffffffu, l[m2][i], 2);
        }
        const float inv0 = 1.0f / l[m2][0], inv1 = 1.0f / l[m2][1];
        const int rl = qt * 128 + m0 + m2 * 16 + tq;
        __half* og = g_att + ((long)b * Sc + rl) * HID + hd * 64;
        #pragma unroll
        for (int nt = 0; nt < 8; nt++) {
            const int col = nt * 8 + tr * 2;
            *(__half2*)(og + col)           = __floats2half2_rn(o[m2][nt][0] * inv0, o[m2][nt][1] * inv0);
            *(__half2*)(og + 8 * HID + col) = __floats2half2_rn(o[m2][nt][2] * inv1, o[m2][nt][3] * inv1);
        }
    }
}

// ---------------------------------------------------------------------------
// Kernel 3: out = att @ Wo^T + bo, fp16 GEMM (R8 version: 256 thr, M=16/warp).
// ---------------------------------------------------------------------------
constexpr int OP_SMEM = 65536;

__global__ __launch_bounds__(256, 2) void outproj_kernel(
    const float* __restrict__ bo, float* __restrict__ out)
{
    extern __shared__ char sm[];
    const uint32_t sb = smem_u32(sm);
    const int tid = threadIdx.x, lane = tid & 31, w = tid >> 5;
    const int r0 = blockIdx.x * 128, c0 = blockIdx.y * 128;
    const int lr = lane & 7, g = lane >> 3, tq = lane >> 2, tr = lane & 3;
    const int m0 = w * 16;

    auto prefetch = [&](int kt) {
        const uint32_t base = sb + (kt & 1) * 32768;
        const char* ag = (const char*)(g_att + (long)r0 * HID + kt * 64);
        const char* bg = (const char*)(g_wo  + (long)c0 * HID + kt * 64);
        for (int i = tid; i < 1024; i += 256) {
            const int row = i >> 3, q = i & 7;
            const uint32_t off = SW((uint32_t)(row * 128 + q * 16));
            cp16(base + off,         ag + (long)row * (HID * 2) + q * 16);
            cp16(base + 16384 + off, bg + (long)row * (HID * 2) + q * 16);
        }
    };

    prefetch(0);
    cp_commit();

    float c[16][4] = {};

    for (int kt = 0; kt < 16; kt++) {
        if (kt < 15) { prefetch(kt + 1); cp_commit(); cp_wait<1>(); }
        else         { cp_wait<0>(); }
        __syncthreads();

        const uint32_t ab = sb + (kt & 1) * 32768;
        const uint32_t bb = ab + 16384;

        uint32_t aa[16];
        #pragma unroll
        for (int kc = 0; kc < 4; kc++)
            ldsm4(aa + kc * 4, ab + SW((m0 + lr + (g & 1) * 8) * 128 + kc * 32 + (g >> 1) * 16));

        #pragma unroll
        for (int nt = 0; nt < 16; nt++) {
            uint32_t bbr[8];
            ldsm4(bbr,     bb + SW((nt * 8 + lr) * 128 + g * 16));
            ldsm4(bbr + 4, bb + SW((nt * 8 + lr) * 128 + g * 16 + 64));
            #pragma unroll
            for (int kc = 0; kc < 4; kc++) mma16816(c[nt], aa + 4 * kc, bbr + 2 * kc);
        }
        __syncthreads();
    }

    const int rl = r0 + m0 + tq;
    #pragma unroll
    for (int nt = 0; nt < 16; nt++) {
        const int col = c0 + nt * 8 + tr * 2;
        const float b0 = bo[col], b1 = bo[col + 1];
        *(float2*)(out + (long)rl * HID + col)       = make_float2(c[nt][0] + b0, c[nt][1] + b1);
        *(float2*)(out + (long)(rl + 8) * HID + col) = make_float2(c[nt][2] + b0, c[nt][3] + b1);
    }
}

// ---------------------------------------------------------------------------
extern "C" void kernel_launch(void* const* d_in, const int* in_sizes, int n_in,
                              void* d_out, int out_size)
{
    const float* q    = (const float*)d_in[0];
    const float* k    = (const float*)d_in[1];
    const float* v    = (const float*)d_in[2];
    const int*   mask = (const int*)  d_in[3];
    const float* Wq   = (const float*)d_in[4];
    const float* bq   = (const float*)d_in[5];
    const float* Wk   = (const float*)d_in[6];
    const float* bk   = (const float*)d_in[7];
    const float* Wv   = (const float*)d_in[8];
    const float* bv   = (const float*)d_in[9];
    const float* Wo   = (const float*)d_in[10];
    const float* bo   = (const float*)d_in[11];
    float* out = (float*)d_out;

    cudaFuncSetAttribute(attn_kernel, cudaFuncAttributeMaxDynamicSharedMemorySize, ATT_SMEM);
    cudaFuncSetAttribute(outproj_kernel, cudaFuncAttributeMaxDynamicSharedMemorySize, OP_SMEM);

    prologue_kernel<<<PRO_GRID, 256>>>(q, k, v, Wq, bq, Wk, bk, Wv, bv, mask, Wo);
    attn_kernel<<<512, 128, ATT_SMEM>>>();
    outproj_kernel<<<dim3(32, 8), 256, OP_SMEM>>>(bo, out);
}

// round 13
// speedup vs baseline: 1.1943x; 1.0480x over previous
#include <cuda_runtime.h>
#include <cuda_fp16.h>
#include <cstdint>

// ---------------- problem constants ----------------
constexpr int Bc = 2;
constexpr int Sc = 2048;
constexpr int Hc = 16;
constexpr int Dc = 64;
constexpr int HID = 1024;
constexpr float CE = 0.03125f * 1.44269504088896340736f;  // (1/sqrt(1024)) * log2(e)

// ---------------- device scratch ----------------
__device__ __half   g_q[Bc * Hc * Sc * Dc];        // [B,H,S,D] fp16 (PRE-SCALED by CE)
__device__ __half   g_k[Bc * Hc * Sc * Dc];        // [B,H,S,D] fp16
__device__ __half   g_v[Bc * Hc * Sc * Dc];        // [B,H,S,D] fp16
__device__ __half   g_att[Bc * Sc * HID];          // [B,S,HID] fp16
__device__ __half   g_wo[HID * HID];               // Wo fp16
__device__ uint32_t g_maskp[Bc * Sc * (Sc / 32)];  // bit-packed mask

// ---------------- helpers ----------------
__device__ __forceinline__ uint32_t smem_u32(const void* p) {
    uint32_t a;
    asm("{ .reg .u64 t; cvta.to.shared.u64 t, %1; cvt.u32.u64 %0, t; }" : "=r"(a) : "l"(p));
    return a;
}
__device__ __forceinline__ uint32_t SW(uint32_t x) { return x ^ ((x >> 3) & 0x70); }

__device__ __forceinline__ void ldsm4(uint32_t* r, uint32_t a) {
    asm volatile("ldmatrix.sync.aligned.m8n8.x4.shared.b16 {%0,%1,%2,%3}, [%4];"
                 : "=r"(r[0]), "=r"(r[1]), "=r"(r[2]), "=r"(r[3]) : "r"(a));
}
__device__ __forceinline__ void ldsm4t(uint32_t* r, uint32_t a) {
    asm volatile("ldmatrix.sync.aligned.m8n8.x4.trans.shared.b16 {%0,%1,%2,%3}, [%4];"
                 : "=r"(r[0]), "=r"(r[1]), "=r"(r[2]), "=r"(r[3]) : "r"(a));
}
__device__ __forceinline__ void mma16816(float* c, const uint32_t* a, const uint32_t* b) {
    asm volatile("mma.sync.aligned.m16n8k16.row.col.f32.f16.f16.f32 "
                 "{%0,%1,%2,%3}, {%4,%5,%6,%7}, {%8,%9}, {%0,%1,%2,%3};"
                 : "+f"(c[0]), "+f"(c[1]), "+f"(c[2]), "+f"(c[3])
                 : "r"(a[0]), "r"(a[1]), "r"(a[2]), "r"(a[3]), "r"(b[0]), "r"(b[1]));
}
// f16-accumulator variant
__device__ __forceinline__ void mma16816h(uint32_t* c, const uint32_t* a, const uint32_t* b) {
    asm volatile("mma.sync.aligned.m16n8k16.row.col.f16.f16.f16.f16 "
                 "{%0,%1}, {%2,%3,%4,%5}, {%6,%7}, {%0,%1};"
                 : "+r"(c[0]), "+r"(c[1])
                 : "r"(a[0]), "r"(a[1]), "r"(a[2]), "r"(a[3]), "r"(b[0]), "r"(b[1]));
}
__device__ __forceinline__ void cp16(uint32_t d, const void* s) {
    asm volatile("cp.async.cg.shared.global [%0], [%1], 16;" :: "r"(d), "l"(s) : "memory");
}
__device__ __forceinline__ void cp_commit() {
    asm volatile("cp.async.commit_group;" ::: "memory");
}
template <int N> __device__ __forceinline__ void cp_wait() {
    asm volatile("cp.async.wait_group %0;" :: "n"(N) : "memory");
}
__device__ __forceinline__ uint32_t ex2_h2(uint32_t x) {
    uint32_t r;
    asm("ex2.approx.f16x2 %0, %1;" : "=r"(r) : "r"(x));
    return r;
}
__device__ __forceinline__ uint32_t hadd2u(uint32_t a, uint32_t b) {
    uint32_t r;
    asm("add.f16x2 %0, %1, %2;" : "=r"(r) : "r"(a), "r"(b));
    return r;
}

// ---------------------------------------------------------------------------
// Fused prologue kernel (R11): proj | mask pack | Wo convert in one launch.
// ---------------------------------------------------------------------------
constexpr int PRO_PROJ_BLOCKS = 1536;
constexpr int PRO_PACK_BLOCKS = 4096;
constexpr int PRO_CONV_BLOCKS = 1024;
constexpr int PRO_GRID = PRO_PROJ_BLOCKS + PRO_PACK_BLOCKS + PRO_CONV_BLOCKS;

__global__ __launch_bounds__(256) void prologue_kernel(
    const float* __restrict__ xq, const float* __restrict__ xk, const float* __restrict__ xv,
    const float* __restrict__ Wq, const float* __restrict__ bq,
    const float* __restrict__ Wk, const float* __restrict__ bk,
    const float* __restrict__ Wv, const float* __restrict__ bv,
    const int* __restrict__ mask, const float* __restrict__ Wo)
{
    const int bid = blockIdx.x;
    const int tid = threadIdx.x;

    if (bid >= PRO_PROJ_BLOCKS + PRO_PACK_BLOCKS) {
        long i = (long)(bid - PRO_PROJ_BLOCKS - PRO_PACK_BLOCKS) * 256 + tid;
        float4 f = ((const float4*)Wo)[i];
        ((__half2*)g_wo)[i * 2]     = __floats2half2_rn(f.x, f.y);
        ((__half2*)g_wo)[i * 2 + 1] = __floats2half2_rn(f.z, f.w);
        return;
    }
    if (bid >= PRO_PROJ_BLOCKS) {
        long t = (long)(bid - PRO_PROJ_BLOCKS) * 256 + tid;
        const int4* mp = (const int4*)(mask + t * 8);
        int4 a = mp[0], b = mp[1];
        uint32_t byte =
            (uint32_t)(a.x != 0)       | ((uint32_t)(a.y != 0) << 1) |
            ((uint32_t)(a.z != 0) << 2) | ((uint32_t)(a.w != 0) << 3) |
            ((uint32_t)(b.x != 0) << 4) | ((uint32_t)(b.y != 0) << 5) |
            ((uint32_t)(b.z != 0) << 6) | ((uint32_t)(b.w != 0) << 7);
        ((uint8_t*)g_maskp)[t] = (uint8_t)byte;
        return;
    }

    __shared__ __half Xs[128 * 64];
    __shared__ __half Ws[64 * 64];
    __shared__ float  bs[64];

    const int which = bid >> 9;
    const int bx = bid & 511;
    const float* X    = (which == 0) ? xq : (which == 1) ? xk : xv;
    const float* Wt   = (which == 0) ? Wq : (which == 1) ? Wk : Wv;
    const float* bias = (which == 0) ? bq : (which == 1) ? bk : bv;
    __half* outp      = (which == 0) ? g_q : (which == 1) ? g_k : g_v;
    const float oscale = (which == 0) ? CE : 1.0f;

    const int lane = tid & 31, w = tid >> 5;
    const long R0 = (long)bx * 128;

    const uint32_t xb = smem_u32(Xs), wb = smem_u32(Ws);
    const float4* Xg = (const float4*)(X + R0 * 64);
    for (int i = tid; i < 2048; i += 256) {
        float4 f = Xg[i];
        uint32_t off = SW((uint32_t)i * 8);
        *(__half2*)((char*)Xs + off)     = __floats2half2_rn(f.x, f.y);
        *(__half2*)((char*)Xs + off + 4) = __floats2half2_rn(f.z, f.w);
    }
    const float4* Wg = (const float4*)Wt;
    for (int i = tid; i < 1024; i += 256) {
        float4 f = Wg[i];
        uint32_t off = SW((uint32_t)i * 8);
        *(__half2*)((char*)Ws + off)     = __floats2half2_rn(f.x, f.y);
        *(__half2*)((char*)Ws + off + 4) = __floats2half2_rn(f.z, f.w);
    }
    if (tid < 64) bs[tid] = bias[tid];
    __syncthreads();

    const int lr = lane & 7, g = lane >> 3, tq = lane >> 2, tr = lane & 3;
    const int m0 = w * 16;

    uint32_t qa[16];
    #pragma unroll
    for (int kc = 0; kc < 4; kc++)
        ldsm4(qa + kc * 4, xb + SW((m0 + lr + (g & 1) * 8) * 128 + kc * 32 + (g >> 1) * 16));

    float c[8][4] = {};
    #pragma unroll
    for (int nt = 0; nt < 8; nt++) {
        uint32_t bk[8];
        ldsm4(bk,     wb + SW((nt * 8 + lr) * 128 + g * 16));
        ldsm4(bk + 4, wb + SW((nt * 8 + lr) * 128 + g * 16 + 64));
        #pragma unroll
        for (int kc = 0; kc < 4; kc++) mma16816(c[nt], qa + 4 * kc, bk + 2 * kc);
    }

    const long Rw = R0 + m0;
    const int b = (int)(Rw >> 15);
    const int s = (int)((Rw >> 4) & 2047);
    #pragma unroll
    for (int nt = 0; nt < 8; nt++) {
        const int col = nt * 8 + tr * 2;
        const float b0 = bs[col], b1 = bs[col + 1];
        const int hl = tq, hh = tq + 8;
        __half2* lo = (__half2*)(outp + (((long)(b * Hc + hl) * Sc + s) * Dc) + col);
        __half2* hi = (__half2*)(outp + (((long)(b * Hc + hh) * Sc + s) * Dc) + col);
        *lo = __floats2half2_rn((c[nt][0] + b0) * oscale, (c[nt][1] + b1) * oscale);
        *hi = __floats2half2_rn((c[nt][2] + b0) * oscale, (c[nt][3] + b1) * oscale);
    }
}

// ---------------------------------------------------------------------------
// Kernel 2: flash attention. 128-thr CTAs, M=32 rows/warp, f16-accum QK.
// 128-key tiles, double-buffered (ONE barrier per 128 keys, was two).
// smem: Q staging 16K (-> mask ring 2x2K) | K 2x16K | V 2x16K = 80 KB.
// ---------------------------------------------------------------------------
constexpr int ATT_SMEM = 81920;
constexpr int ATT_K    = 16384;
constexpr int ATT_V    = 49152;

__global__ __launch_bounds__(128, 2) void attn_kernel()
{
    extern __shared__ char sm[];
    const uint32_t sb = smem_u32(sm);
    const int tid = threadIdx.x, lane = tid & 31, w = tid >> 5;
    const int bh = blockIdx.x >> 4, qt = blockIdx.x & 15;
    const int b = bh >> 4, hd = bh & 15;

    const __half* Qg = g_q + ((long)bh * Sc + qt * 128) * Dc;
    const __half* Kg = g_k + (long)bh * Sc * Dc;
    const __half* Vg = g_v + (long)bh * Sc * Dc;
    const uint32_t* Mp = g_maskp + ((long)b * Sc + qt * 128) * (Sc / 32);

    // ---- prologue: Q tile (128 rows x 128B = 16KB) into [0, 16384) ----
    for (int i = tid; i < 1024; i += 128)
        cp16(sb + (((uint32_t)i * 16) & ~1023u) + SW(((uint32_t)i * 16) & 1023u),
             (const char*)Qg + (long)i * 16);
    cp_commit();
    cp_wait<0>();
    __syncthreads();

    const int lr = lane & 7, g = lane >> 3, tq = lane >> 2, tr = lane & 3;
    const int m0 = w * 32;

    uint32_t qa[2][16];
    #pragma unroll
    for (int m2 = 0; m2 < 2; m2++)
        #pragma unroll
        for (int kc = 0; kc < 4; kc++)
            ldsm4(qa[m2] + kc * 4,
                  sb + SW((m0 + m2 * 16 + lr + (g & 1) * 8) * 128 + kc * 32 + (g >> 1) * 16));
    __syncthreads();   // Q area dead -> mask ring (2 x 2KB)

    // prefetch one 128-key tile (K 16KB + V 16KB + mask 2KB)
    auto prefetch = [&](int t, int slot) {
        const uint32_t kb = sb + ATT_K + slot * 16384;
        const uint32_t vb = sb + ATT_V + slot * 16384;
        const char* kg = (const char*)(Kg + (long)t * 128 * 64);
        const char* vg = (const char*)(Vg + (long)t * 128 * 64);
        #pragma unroll
        for (int r = 0; r < 8; r++) {
            const int i = tid + r * 128;
            uint32_t off = (((uint32_t)i * 16) & ~1023u) + SW(((uint32_t)i * 16) & 1023u);
            cp16(kb + off, kg + (long)i * 16);
            cp16(vb + off, vg + (long)i * 16);
        }
        cp16(sb + slot * 2048 + tid * 16, (const char*)(Mp + (long)tid * 64 + t * 4));
    };

    prefetch(0, 0);
    cp_commit();

    float o[2][8][4] = {};
    float l[2][2] = {};

    for (int t = 0; t < 16; t++) {
        const int slot = t & 1;
        cp_wait<0>();
        __syncthreads();   // tile t visible; all warps done with slot (t+1)&1

        if (t < 15) { prefetch(t + 1, slot ^ 1); cp_commit(); }

        const uint32_t* mrow = (const uint32_t*)(sm + slot * 2048);

        // ---- two 64-key sub-tiles ----
        #pragma unroll
        for (int s = 0; s < 2; s++) {
            const uint32_t kb = sb + ATT_K + slot * 16384 + s * 8192;
            const uint32_t vb = sb + ATT_V + slot * 16384 + s * 8192;

            uint32_t pa[2][16];
            uint32_t lacc[2][2] = {{0, 0}, {0, 0}};

            // QK (f16 accum) + exp + mask-zero, two N-halves of the sub-tile
            #pragma unroll
            for (int h = 0; h < 2; h++) {
                uint32_t wa_m[2], wb_m[2];
                #pragma unroll
                for (int m2 = 0; m2 < 2; m2++) {
                    const int ra = m0 + m2 * 16 + tq;
                    wa_m[m2] = mrow[ra * 4 + s * 2 + h]       >> (tr * 2);
                    wb_m[m2] = mrow[(ra + 8) * 4 + s * 2 + h] >> (tr * 2);
                }
                #pragma unroll
                for (int j = 0; j < 4; j++) {
                    const int nt = h * 4 + j;
                    uint32_t bkj[8];
                    ldsm4(bkj,     kb + SW((nt * 8 + lr) * 128 + g * 16));
                    ldsm4(bkj + 4, kb + SW((nt * 8 + lr) * 128 + g * 16 + 64));
                    const int sh = j << 3;
                    #pragma unroll
                    for (int m2 = 0; m2 < 2; m2++) {
                        uint32_t cd[2] = {0u, 0u};
                        #pragma unroll
                        for (int kc = 0; kc < 4; kc++)
                            mma16816h(cd, qa[m2] + 4 * kc, bkj + 2 * kc);
                        const uint32_t wa = wa_m[m2] >> sh;
                        const uint32_t wbv = wb_m[m2] >> sh;
                        const uint32_t keep01 = ((wa & 1u)  ? 0x0000FFFFu : 0u) |
                                                ((wa & 2u)  ? 0xFFFF0000u : 0u);
                        const uint32_t keep23 = ((wbv & 1u) ? 0x0000FFFFu : 0u) |
                                                ((wbv & 2u) ? 0xFFFF0000u : 0u);
                        uint32_t p01 = ex2_h2(cd[0]) & keep01;
                        uint32_t p23 = ex2_h2(cd[1]) & keep23;
                        pa[m2][nt * 2]     = p01;
                        pa[m2][nt * 2 + 1] = p23;
                        lacc[m2][0] = hadd2u(lacc[m2][0], p01);
                        lacc[m2][1] = hadd2u(lacc[m2][1], p23);
                    }
                }
            }

            #pragma unroll
            for (int m2 = 0; m2 < 2; m2++) {
                float2 f0 = __half22float2(*reinterpret_cast<__half2*>(&lacc[m2][0]));
                float2 f1 = __half22float2(*reinterpret_cast<__half2*>(&lacc[m2][1]));
                l[m2][0] += f0.x + f0.y;
                l[m2][1] += f1.x + f1.y;
            }

            // O += P @ V (fp32 accum)
            #pragma unroll
            for (int nt = 0; nt < 8; nt++) {
                uint32_t bv[8];
                ldsm4t(bv,     vb + SW((g * 8 + lr) * 128 + nt * 16));
                ldsm4t(bv + 4, vb + SW((g * 8 + lr + 32) * 128 + nt * 16));
                #pragma unroll
                for (int m2 = 0; m2 < 2; m2++)
                    #pragma unroll
                    for (int kc = 0; kc < 4; kc++)
                        mma16816(o[m2][nt], pa[m2] + 4 * kc, bv + 2 * kc);
            }
        }
    }

    #pragma unroll
    for (int m2 = 0; m2 < 2; m2++) {
        #pragma unroll
        for (int i = 0; i < 2; i++) {
            l[m2][i] += __shfl_xor_sync(0xffffffffu, l[m2][i], 1);
            l[m2][i] += __shfl_xor_sync(0xffffffffu, l[m2][i], 2);
        }
        const float inv0 = 1.0f / l[m2][0], inv1 = 1.0f / l[m2][1];
        const int rl = qt * 128 + m0 + m2 * 16 + tq;
        __half* og = g_att + ((long)b * Sc + rl) * HID + hd * 64;
        #pragma unroll
        for (int nt = 0; nt < 8; nt++) {
            const int col = nt * 8 + tr * 2;
            *(__half2*)(og + col)           = __floats2half2_rn(o[m2][nt][0] * inv0, o[m2][nt][1] * inv0);
            *(__half2*)(og + 8 * HID + col) = __floats2half2_rn(o[m2][nt][2] * inv1, o[m2][nt][3] * inv1);
        }
    }
}

// ---------------------------------------------------------------------------
// Kernel 3: out = att @ Wo^T + bo, fp16 GEMM (R8/R11 version).
// ---------------------------------------------------------------------------
constexpr int OP_SMEM = 65536;

__global__ __launch_bounds__(256, 2) void outproj_kernel(
    const float* __restrict__ bo, float* __restrict__ out)
{
    extern __shared__ char sm[];
    const uint32_t sb = smem_u32(sm);
    const int tid = threadIdx.x, lane = tid & 31, w = tid >> 5;
    const int r0 = blockIdx.x * 128, c0 = blockIdx.y * 128;
    const int lr = lane & 7, g = lane >> 3, tq = lane >> 2, tr = lane & 3;
    const int m0 = w * 16;

    auto prefetch = [&](int kt) {
        const uint32_t base = sb + (kt & 1) * 32768;
        const char* ag = (const char*)(g_att + (long)r0 * HID + kt * 64);
        const char* bg = (const char*)(g_wo  + (long)c0 * HID + kt * 64);
        for (int i = tid; i < 1024; i += 256) {
            const int row = i >> 3, q = i & 7;
            const uint32_t off = SW((uint32_t)(row * 128 + q * 16));
            cp16(base + off,         ag + (long)row * (HID * 2) + q * 16);
            cp16(base + 16384 + off, bg + (long)row * (HID * 2) + q * 16);
        }
    };

    prefetch(0);
    cp_commit();

    float c[16][4] = {};

    for (int kt = 0; kt < 16; kt++) {
        if (kt < 15) { prefetch(kt + 1); cp_commit(); cp_wait<1>(); }
        else         { cp_wait<0>(); }
        __syncthreads();

        const uint32_t ab = sb + (kt & 1) * 32768;
        const uint32_t bb = ab + 16384;

        uint32_t aa[16];
        #pragma unroll
        for (int kc = 0; kc < 4; kc++)
            ldsm4(aa + kc * 4, ab + SW((m0 + lr + (g & 1) * 8) * 128 + kc * 32 + (g >> 1) * 16));

        #pragma unroll
        for (int nt = 0; nt < 16; nt++) {
            uint32_t bbr[8];
            ldsm4(bbr,     bb + SW((nt * 8 + lr) * 128 + g * 16));
            ldsm4(bbr + 4, bb + SW((nt * 8 + lr) * 128 + g * 16 + 64));
            #pragma unroll
            for (int kc = 0; kc < 4; kc++) mma16816(c[nt], aa + 4 * kc, bbr + 2 * kc);
        }
        __syncthreads();
    }

    const int rl = r0 + m0 + tq;
    #pragma unroll
    for (int nt = 0; nt < 16; nt++) {
        const int col = c0 + nt * 8 + tr * 2;
        const float b0 = bo[col], b1 = bo[col + 1];
        *(float2*)(out + (long)rl * HID + col)       = make_float2(c[nt][0] + b0, c[nt][1] + b1);
        *(float2*)(out + (long)(rl + 8) * HID + col) = make_float2(c[nt][2] + b0, c[nt][3] + b1);
    }
}

// ---------------------------------------------------------------------------
extern "C" void kernel_launch(void* const* d_in, const int* in_sizes, int n_in,
                              void* d_out, int out_size)
{
    const float* q    = (const float*)d_in[0];
    const float* k    = (const float*)d_in[1];
    const float* v    = (const float*)d_in[2];
    const int*   mask = (const int*)  d_in[3];
    const float* Wq   = (const float*)d_in[4];
    const float* bq   = (const float*)d_in[5];
    const float* Wk   = (const float*)d_in[6];
    const float* bk   = (const float*)d_in[7];
    const float* Wv   = (const float*)d_in[8];
    const float* bv   = (const float*)d_in[9];
    const float* Wo   = (const float*)d_in[10];
    const float* bo   = (const float*)d_in[11];
    float* out = (float*)d_out;

    cudaFuncSetAttribute(attn_kernel, cudaFuncAttributeMaxDynamicSharedMemorySize, ATT_SMEM);
    cudaFuncSetAttribute(outproj_kernel, cudaFuncAttributeMaxDynamicSharedMemorySize, OP_SMEM);

    prologue_kernel<<<PRO_GRID, 256>>>(q, k, v, Wq, bq, Wk, bk, Wv, bv, mask, Wo);
    attn_kernel<<<512, 128, ATT_SMEM>>>();
    outproj_kernel<<<dim3(32, 8), 256, OP_SMEM>>>(bo, out);
}

// round 14
// speedup vs baseline: 1.1961x; 1.0015x over previous
#include <cuda_runtime.h>
#include <cuda_fp16.h>
#include <cstdint>

// ---------------- problem constants ----------------
constexpr int Bc = 2;
constexpr int Sc = 2048;
constexpr int Hc = 16;
constexpr int Dc = 64;
constexpr int HID = 1024;
constexpr float CE = 0.03125f * 1.44269504088896340736f;  // (1/sqrt(1024)) * log2(e)

// ---------------- device scratch ----------------
__device__ __half   g_q[Bc * Hc * Sc * Dc];        // [B,H,S,D] fp16 (PRE-SCALED by CE)
__device__ __half   g_k[Bc * Hc * Sc * Dc];        // [B,H,S,D] fp16
__device__ __half   g_v[Bc * Hc * Sc * Dc];        // [B,H,S,D] fp16
__device__ __half   g_att[Bc * Sc * HID];          // [B,S,HID] fp16
__device__ __half   g_wo[HID * HID];               // Wo fp16
__device__ uint32_t g_maskp[Bc * Sc * (Sc / 32)];  // bit-packed mask

// ---------------- helpers ----------------
__device__ __forceinline__ uint32_t smem_u32(const void* p) {
    uint32_t a;
    asm("{ .reg .u64 t; cvta.to.shared.u64 t, %1; cvt.u32.u64 %0, t; }" : "=r"(a) : "l"(p));
    return a;
}
__device__ __forceinline__ uint32_t SW(uint32_t x) { return x ^ ((x >> 3) & 0x70); }

__device__ __forceinline__ void ldsm4(uint32_t* r, uint32_t a) {
    asm volatile("ldmatrix.sync.aligned.m8n8.x4.shared.b16 {%0,%1,%2,%3}, [%4];"
                 : "=r"(r[0]), "=r"(r[1]), "=r"(r[2]), "=r"(r[3]) : "r"(a));
}
__device__ __forceinline__ void ldsm4t(uint32_t* r, uint32_t a) {
    asm volatile("ldmatrix.sync.aligned.m8n8.x4.trans.shared.b16 {%0,%1,%2,%3}, [%4];"
                 : "=r"(r[0]), "=r"(r[1]), "=r"(r[2]), "=r"(r[3]) : "r"(a));
}
__device__ __forceinline__ void mma16816(float* c, const uint32_t* a, const uint32_t* b) {
    asm volatile("mma.sync.aligned.m16n8k16.row.col.f32.f16.f16.f32 "
                 "{%0,%1,%2,%3}, {%4,%5,%6,%7}, {%8,%9}, {%0,%1,%2,%3};"
                 : "+f"(c[0]), "+f"(c[1]), "+f"(c[2]), "+f"(c[3])
                 : "r"(a[0]), "r"(a[1]), "r"(a[2]), "r"(a[3]), "r"(b[0]), "r"(b[1]));
}
// f16-accumulator variant
__device__ __forceinline__ void mma16816h(uint32_t* c, const uint32_t* a, const uint32_t* b) {
    asm volatile("mma.sync.aligned.m16n8k16.row.col.f16.f16.f16.f16 "
                 "{%0,%1}, {%2,%3,%4,%5}, {%6,%7}, {%0,%1};"
                 : "+r"(c[0]), "+r"(c[1])
                 : "r"(a[0]), "r"(a[1]), "r"(a[2]), "r"(a[3]), "r"(b[0]), "r"(b[1]));
}
__device__ __forceinline__ void cp16(uint32_t d, const void* s) {
    asm volatile("cp.async.cg.shared.global [%0], [%1], 16;" :: "r"(d), "l"(s) : "memory");
}
__device__ __forceinline__ void cp_commit() {
    asm volatile("cp.async.commit_group;" ::: "memory");
}
template <int N> __device__ __forceinline__ void cp_wait() {
    asm volatile("cp.async.wait_group %0;" :: "n"(N) : "memory");
}
__device__ __forceinline__ uint32_t ex2_h2(uint32_t x) {
    uint32_t r;
    asm("ex2.approx.f16x2 %0, %1;" : "=r"(r) : "r"(x));
    return r;
}
__device__ __forceinline__ uint32_t hadd2u(uint32_t a, uint32_t b) {
    uint32_t r;
    asm("add.f16x2 %0, %1, %2;" : "=r"(r) : "r"(a), "r"(b));
    return r;
}

// ---------------------------------------------------------------------------
// Fused prologue kernel: proj | mask pack (32 elems/thr, MLP=8) |
// Wo convert (16 floats/thr, MLP=4) in one launch.
// ---------------------------------------------------------------------------
constexpr int PRO_PROJ_BLOCKS = 1536;
constexpr int PRO_PACK_BLOCKS = 1024;   // 262144 words / 256 thr
constexpr int PRO_CONV_BLOCKS = 256;    // 262144 float4 / (256 thr * 4)
constexpr int PRO_GRID = PRO_PROJ_BLOCKS + PRO_PACK_BLOCKS + PRO_CONV_BLOCKS;

__global__ __launch_bounds__(256) void prologue_kernel(
    const float* __restrict__ xq, const float* __restrict__ xk, const float* __restrict__ xv,
    const float* __restrict__ Wq, const float* __restrict__ bq,
    const float* __restrict__ Wk, const float* __restrict__ bk,
    const float* __restrict__ Wv, const float* __restrict__ bv,
    const int* __restrict__ mask, const float* __restrict__ Wo)
{
    const int bid = blockIdx.x;
    const int tid = threadIdx.x;

    if (bid >= PRO_PROJ_BLOCKS + PRO_PACK_BLOCKS) {
        // ---- Wo fp32 -> fp16, 4 independent float4 loads per thread ----
        long t = (long)(bid - PRO_PROJ_BLOCKS - PRO_PACK_BLOCKS) * 256 + tid;
        const float4* src = (const float4*)Wo + t * 4;
        float4 f[4];
        #pragma unroll
        for (int c = 0; c < 4; c++) f[c] = src[c];
        __half2* dst = (__half2*)g_wo + t * 8;
        #pragma unroll
        for (int c = 0; c < 4; c++) {
            dst[c * 2]     = __floats2half2_rn(f[c].x, f[c].y);
            dst[c * 2 + 1] = __floats2half2_rn(f[c].z, f[c].w);
        }
        return;
    }
    if (bid >= PRO_PROJ_BLOCKS) {
        // ---- mask bit-pack: 32 elems -> 1 word per thread (8 int4 loads) ----
        long t = (long)(bid - PRO_PROJ_BLOCKS) * 256 + tid;
        const int4* mp = (const int4*)(mask + t * 32);
        int4 v[8];
        #pragma unroll
        for (int c = 0; c < 8; c++) v[c] = mp[c];
        uint32_t bits = 0;
        #pragma unroll
        for (int c = 0; c < 8; c++) {
            bits |= ((uint32_t)(v[c].x != 0) << (c * 4))
                 |  ((uint32_t)(v[c].y != 0) << (c * 4 + 1))
                 |  ((uint32_t)(v[c].z != 0) << (c * 4 + 2))
                 |  ((uint32_t)(v[c].w != 0) << (c * 4 + 3));
        }
        g_maskp[t] = bits;
        return;
    }

    // ---- QKV projection (fp16 mma; Q pre-scaled by CE) ----
    __shared__ __half Xs[128 * 64];
    __shared__ __half Ws[64 * 64];
    __shared__ float  bs[64];

    const int which = bid >> 9;
    const int bx = bid & 511;
    const float* X    = (which == 0) ? xq : (which == 1) ? xk : xv;
    const float* Wt   = (which == 0) ? Wq : (which == 1) ? Wk : Wv;
    const float* bias = (which == 0) ? bq : (which == 1) ? bk : bv;
    __half* outp      = (which == 0) ? g_q : (which == 1) ? g_k : g_v;
    const float oscale = (which == 0) ? CE : 1.0f;

    const int lane = tid & 31, w = tid >> 5;
    const long R0 = (long)bx * 128;

    const uint32_t xb = smem_u32(Xs), wb = smem_u32(Ws);
    const float4* Xg = (const float4*)(X + R0 * 64);
    for (int i = tid; i < 2048; i += 256) {
        float4 f = Xg[i];
        uint32_t off = SW((uint32_t)i * 8);
        *(__half2*)((char*)Xs + off)     = __floats2half2_rn(f.x, f.y);
        *(__half2*)((char*)Xs + off + 4) = __floats2half2_rn(f.z, f.w);
    }
    const float4* Wg = (const float4*)Wt;
    for (int i = tid; i < 1024; i += 256) {
        float4 f = Wg[i];
        uint32_t off = SW((uint32_t)i * 8);
        *(__half2*)((char*)Ws + off)     = __floats2half2_rn(f.x, f.y);
        *(__half2*)((char*)Ws + off + 4) = __floats2half2_rn(f.z, f.w);
    }
    if (tid < 64) bs[tid] = bias[tid];
    __syncthreads();

    const int lr = lane & 7, g = lane >> 3, tq = lane >> 2, tr = lane & 3;
    const int m0 = w * 16;

    uint32_t qa[16];
    #pragma unroll
    for (int kc = 0; kc < 4; kc++)
        ldsm4(qa + kc * 4, xb + SW((m0 + lr + (g & 1) * 8) * 128 + kc * 32 + (g >> 1) * 16));

    float c[8][4] = {};
    #pragma unroll
    for (int nt = 0; nt < 8; nt++) {
        uint32_t bk[8];
        ldsm4(bk,     wb + SW((nt * 8 + lr) * 128 + g * 16));
        ldsm4(bk + 4, wb + SW((nt * 8 + lr) * 128 + g * 16 + 64));
        #pragma unroll
        for (int kc = 0; kc < 4; kc++) mma16816(c[nt], qa + 4 * kc, bk + 2 * kc);
    }

    const long Rw = R0 + m0;
    const int b = (int)(Rw >> 15);
    const int s = (int)((Rw >> 4) & 2047);
    #pragma unroll
    for (int nt = 0; nt < 8; nt++) {
        const int col = nt * 8 + tr * 2;
        const float b0 = bs[col], b1 = bs[col + 1];
        const int hl = tq, hh = tq + 8;
        __half2* lo = (__half2*)(outp + (((long)(b * Hc + hl) * Sc + s) * Dc) + col);
        __half2* hi = (__half2*)(outp + (((long)(b * Hc + hh) * Sc + s) * Dc) + col);
        *lo = __floats2half2_rn((c[nt][0] + b0) * oscale, (c[nt][1] + b1) * oscale);
        *hi = __floats2half2_rn((c[nt][2] + b0) * oscale, (c[nt][3] + b1) * oscale);
    }
}

// ---------------------------------------------------------------------------
// Kernel 2: flash attention (R13 best). 128-thr CTAs, M=32 rows/warp,
// f16-accum QK, 128-key double-buffered tiles, one barrier per tile.
// smem: Q staging 16K (-> mask ring 2x2K) | K 2x16K | V 2x16K = 80 KB.
// ---------------------------------------------------------------------------
constexpr int ATT_SMEM = 81920;
constexpr int ATT_K    = 16384;
constexpr int ATT_V    = 49152;

__global__ __launch_bounds__(128, 2) void attn_kernel()
{
    extern __shared__ char sm[];
    const uint32_t sb = smem_u32(sm);
    const int tid = threadIdx.x, lane = tid & 31, w = tid >> 5;
    const int bh = blockIdx.x >> 4, qt = blockIdx.x & 15;
    const int b = bh >> 4, hd = bh & 15;

    const __half* Qg = g_q + ((long)bh * Sc + qt * 128) * Dc;
    const __half* Kg = g_k + (long)bh * Sc * Dc;
    const __half* Vg = g_v + (long)bh * Sc * Dc;
    const uint32_t* Mp = g_maskp + ((long)b * Sc + qt * 128) * (Sc / 32);

    // ---- prologue: Q tile (128 rows x 128B = 16KB) into [0, 16384) ----
    for (int i = tid; i < 1024; i += 128)
        cp16(sb + (((uint32_t)i * 16) & ~1023u) + SW(((uint32_t)i * 16) & 1023u),
             (const char*)Qg + (long)i * 16);
    cp_commit();
    cp_wait<0>();
    __syncthreads();

    const int lr = lane & 7, g = lane >> 3, tq = lane >> 2, tr = lane & 3;
    const int m0 = w * 32;

    uint32_t qa[2][16];
    #pragma unroll
    for (int m2 = 0; m2 < 2; m2++)
        #pragma unroll
        for (int kc = 0; kc < 4; kc++)
            ldsm4(qa[m2] + kc * 4,
                  sb + SW((m0 + m2 * 16 + lr + (g & 1) * 8) * 128 + kc * 32 + (g >> 1) * 16));
    __syncthreads();   // Q area dead -> mask ring (2 x 2KB)

    // prefetch one 128-key tile (K 16KB + V 16KB + mask 2KB)
    auto prefetch = [&](int t, int slot) {
        const uint32_t kb = sb + ATT_K + slot * 16384;
        const uint32_t vb = sb + ATT_V + slot * 16384;
        const char* kg = (const char*)(Kg + (long)t * 128 * 64);
        const char* vg = (const char*)(Vg + (long)t * 128 * 64);
        #pragma unroll
        for (int r = 0; r < 8; r++) {
            const int i = tid + r * 128;
            uint32_t off = (((uint32_t)i * 16) & ~1023u) + SW(((uint32_t)i * 16) & 1023u);
            cp16(kb + off, kg + (long)i * 16);
            cp16(vb + off, vg + (long)i * 16);
        }
        cp16(sb + slot * 2048 + tid * 16, (const char*)(Mp + (long)tid * 64 + t * 4));
    };

    prefetch(0, 0);
    cp_commit();

    float o[2][8][4] = {};
    float l[2][2] = {};

    for (int t = 0; t < 16; t++) {
        const int slot = t & 1;
        cp_wait<0>();
        __syncthreads();   // tile t visible; all warps done with slot (t+1)&1

        if (t < 15) { prefetch(t + 1, slot ^ 1); cp_commit(); }

        const uint32_t* mrow = (const uint32_t*)(sm + slot * 2048);

        // ---- two 64-key sub-tiles ----
        #pragma unroll
        for (int s = 0; s < 2; s++) {
            const uint32_t kb = sb + ATT_K + slot * 16384 + s * 8192;
            const uint32_t vb = sb + ATT_V + slot * 16384 + s * 8192;

            uint32_t pa[2][16];
            uint32_t lacc[2][2] = {{0, 0}, {0, 0}};

            // QK (f16 accum) + exp + mask-zero, two N-halves of the sub-tile
            #pragma unroll
            for (int h = 0; h < 2; h++) {
                uint32_t wa_m[2], wb_m[2];
                #pragma unroll
                for (int m2 = 0; m2 < 2; m2++) {
                    const int ra = m0 + m2 * 16 + tq;
                    wa_m[m2] = mrow[ra * 4 + s * 2 + h]       >> (tr * 2);
                    wb_m[m2] = mrow[(ra + 8) * 4 + s * 2 + h] >> (tr * 2);
                }
                #pragma unroll
                for (int j = 0; j < 4; j++) {
                    const int nt = h * 4 + j;
                    uint32_t bkj[8];
                    ldsm4(bkj,     kb + SW((nt * 8 + lr) * 128 + g * 16));
                    ldsm4(bkj + 4, kb + SW((nt * 8 + lr) * 128 + g * 16 + 64));
                    const int sh = j << 3;
                    #pragma unroll
                    for (int m2 = 0; m2 < 2; m2++) {
                        uint32_t cd[2] = {0u, 0u};
                        #pragma unroll
                        for (int kc = 0; kc < 4; kc++)
                            mma16816h(cd, qa[m2] + 4 * kc, bkj + 2 * kc);
                        const uint32_t wa = wa_m[m2] >> sh;
                        const uint32_t wbv = wb_m[m2] >> sh;
                        const uint32_t keep01 = ((wa & 1u)  ? 0x0000FFFFu : 0u) |
                                                ((wa & 2u)  ? 0xFFFF0000u : 0u);
                        const uint32_t keep23 = ((wbv & 1u) ? 0x0000FFFFu : 0u) |
                                                ((wbv & 2u) ? 0xFFFF0000u : 0u);
                        uint32_t p01 = ex2_h2(cd[0]) & keep01;
                        uint32_t p23 = ex2_h2(cd[1]) & keep23;
                        pa[m2][nt * 2]     = p01;
                        pa[m2][nt * 2 + 1] = p23;
                        lacc[m2][0] = hadd2u(lacc[m2][0], p01);
                        lacc[m2][1] = hadd2u(lacc[m2][1], p23);
                    }
                }
            }

            #pragma unroll
            for (int m2 = 0; m2 < 2; m2++) {
                float2 f0 = __half22float2(*reinterpret_cast<__half2*>(&lacc[m2][0]));
                float2 f1 = __half22float2(*reinterpret_cast<__half2*>(&lacc[m2][1]));
                l[m2][0] += f0.x + f0.y;
                l[m2][1] += f1.x + f1.y;
            }

            // O += P @ V (fp32 accum)
            #pragma unroll
            for (int nt = 0; nt < 8; nt++) {
                uint32_t bv[8];
                ldsm4t(bv,     vb + SW((g * 8 + lr) * 128 + nt * 16));
                ldsm4t(bv + 4, vb + SW((g * 8 + lr + 32) * 128 + nt * 16));
                #pragma unroll
                for (int m2 = 0; m2 < 2; m2++)
                    #pragma unroll
                    for (int kc = 0; kc < 4; kc++)
                        mma16816(o[m2][nt], pa[m2] + 4 * kc, bv + 2 * kc);
            }
        }
    }

    #pragma unroll
    for (int m2 = 0; m2 < 2; m2++) {
        #pragma unroll
        for (int i = 0; i < 2; i++) {
            l[m2][i] += __shfl_xor_sync(0xffffffffu, l[m2][i], 1);
            l[m2][i] += __shfl_xor_sync(0xffffffffu, l[m2][i], 2);
        }
        const float inv0 = 1.0f / l[m2][0], inv1 = 1.0f / l[m2][1];
        const int rl = qt * 128 + m0 + m2 * 16 + tq;
        __half* og = g_att + ((long)b * Sc + rl) * HID + hd * 64;
        #pragma unroll
        for (int nt = 0; nt < 8; nt++) {
            const int col = nt * 8 + tr * 2;
            *(__half2*)(og + col)           = __floats2half2_rn(o[m2][nt][0] * inv0, o[m2][nt][1] * inv0);
            *(__half2*)(og + 8 * HID + col) = __floats2half2_rn(o[m2][nt][2] * inv1, o[m2][nt][3] * inv1);
        }
    }
}

// ---------------------------------------------------------------------------
// Kernel 3: out = att @ Wo^T + bo, fp16 GEMM (R8/R11 version).
// ---------------------------------------------------------------------------
constexpr int OP_SMEM = 65536;

__global__ __launch_bounds__(256, 2) void outproj_kernel(
    const float* __restrict__ bo, float* __restrict__ out)
{
    extern __shared__ char sm[];
    const uint32_t sb = smem_u32(sm);
    const int tid = threadIdx.x, lane = tid & 31, w = tid >> 5;
    const int r0 = blockIdx.x * 128, c0 = blockIdx.y * 128;
    const int lr = lane & 7, g = lane >> 3, tq = lane >> 2, tr = lane & 3;
    const int m0 = w * 16;

    auto prefetch = [&](int kt) {
        const uint32_t base = sb + (kt & 1) * 32768;
        const char* ag = (const char*)(g_att + (long)r0 * HID + kt * 64);
        const char* bg = (const char*)(g_wo  + (long)c0 * HID + kt * 64);
        for (int i = tid; i < 1024; i += 256) {
            const int row = i >> 3, q = i & 7;
            const uint32_t off = SW((uint32_t)(row * 128 + q * 16));
            cp16(base + off,         ag + (long)row * (HID * 2) + q * 16);
            cp16(base + 16384 + off, bg + (long)row * (HID * 2) + q * 16);
        }
    };

    prefetch(0);
    cp_commit();

    float c[16][4] = {};

    for (int kt = 0; kt < 16; kt++) {
        if (kt < 15) { prefetch(kt + 1); cp_commit(); cp_wait<1>(); }
        else         { cp_wait<0>(); }
        __syncthreads();

        const uint32_t ab = sb + (kt & 1) * 32768;
        const uint32_t bb = ab + 16384;

        uint32_t aa[16];
        #pragma unroll
        for (int kc = 0; kc < 4; kc++)
            ldsm4(aa + kc * 4, ab + SW((m0 + lr + (g & 1) * 8) * 128 + kc * 32 + (g >> 1) * 16));

        #pragma unroll
        for (int nt = 0; nt < 16; nt++) {
            uint32_t bbr[8];
            ldsm4(bbr,     bb + SW((nt * 8 + lr) * 128 + g * 16));
            ldsm4(bbr + 4, bb + SW((nt * 8 + lr) * 128 + g * 16 + 64));
            #pragma unroll
            for (int kc = 0; kc < 4; kc++) mma16816(c[nt], aa + 4 * kc, bbr + 2 * kc);
        }
        __syncthreads();
    }

    const int rl = r0 + m0 + tq;
    #pragma unroll
    for (int nt = 0; nt < 16; nt++) {
        const int col = c0 + nt * 8 + tr * 2;
        const float b0 = bo[col], b1 = bo[col + 1];
        *(float2*)(out + (long)rl * HID + col)       = make_float2(c[nt][0] + b0, c[nt][1] + b1);
        *(float2*)(out + (long)(rl + 8) * HID + col) = make_float2(c[nt][2] + b0, c[nt][3] + b1);
    }
}

// ---------------------------------------------------------------------------
extern "C" void kernel_launch(void* const* d_in, const int* in_sizes, int n_in,
                              void* d_out, int out_size)
{
    const float* q    = (const float*)d_in[0];
    const float* k    = (const float*)d_in[1];
    const float* v    = (const float*)d_in[2];
    const int*   mask = (const int*)  d_in[3];
    const float* Wq   = (const float*)d_in[4];
    const float* bq   = (const float*)d_in[5];
    const float* Wk   = (const float*)d_in[6];
    const float* bk   = (const float*)d_in[7];
    const float* Wv   = (const float*)d_in[8];
    const float* bv   = (const float*)d_in[9];
    const float* Wo   = (const float*)d_in[10];
    const float* bo   = (const float*)d_in[11];
    float* out = (float*)d_out;

    cudaFuncSetAttribute(attn_kernel, cudaFuncAttributeMaxDynamicSharedMemorySize, ATT_SMEM);
    cudaFuncSetAttribute(outproj_kernel, cudaFuncAttributeMaxDynamicSharedMemorySize, OP_SMEM);

    prologue_kernel<<<PRO_GRID, 256>>>(q, k, v, Wq, bq, Wk, bk, Wv, bv, mask, Wo);
    attn_kernel<<<512, 128, ATT_SMEM>>>();
    outproj_kernel<<<dim3(32, 8), 256, OP_SMEM>>>(bo, out);
}